// round 9
// baseline (speedup 1.0000x reference)
#include <cuda_runtime.h>
#include <math.h>

// Problem dims
#define BB 32
#define SS 2048
#define II 128
#define HH 512
#define OO 128

#define RGRID 128        // persistent recurrence grid (must all be co-resident)
#define HSTRIDE 516      // 512 + 4 pad (conflict-free lane-b strided rows)

// ---------------- static device scratch ----------------
__device__ float g_Abuf[SS * BB * 1536];  // x-projections [t][b][z|r|g]
__device__ float g_H0[SS * BB * HH];
__device__ float g_H1[SS * BB * HH];
__device__ float g_hc[2 * BB * HH];
__device__ float g_rhbuf[BB * HH];

// two-level barrier state: 8 group counters (128B apart), root, release flag
__device__ unsigned g_grp[8 * 32];
__device__ unsigned g_root[32];
__device__ unsigned g_rel[32];

// ---------------- cp.async helpers ----------------
__device__ __forceinline__ void cp_async16(void* smem, const void* gmem) {
    unsigned s = (unsigned)__cvta_generic_to_shared(smem);
    asm volatile("cp.async.cg.shared.global [%0], [%1], 16;" :: "r"(s), "l"(gmem));
}
__device__ __forceinline__ void cp_commit() {
    asm volatile("cp.async.commit_group;");
}
template<int N> __device__ __forceinline__ void cp_wait() {
    asm volatile("cp.async.wait_group %0;" :: "n"(N));
}

// ---------------- two-level grid barrier (split arrive / wait) ----------------
// Caller guarantees __syncthreads() before arrive (cumulativity via bar.sync)
// and calls wait from one thread then __syncthreads().
__device__ __forceinline__ void bar_arrive(int grp) {
    unsigned old;
    asm volatile("atom.acq_rel.gpu.global.add.u32 %0, [%1], %2;"
                 : "=r"(old) : "l"(&g_grp[grp * 32]), "r"(1u) : "memory");
    if (((old + 1) & 15) == 0) {            // last of 16 CTAs in group
        unsigned o2;
        asm volatile("atom.acq_rel.gpu.global.add.u32 %0, [%1], %2;"
                     : "=r"(o2) : "l"(&g_root[0]), "r"(1u) : "memory");
        if (((o2 + 1) & 7) == 0) {          // last of 8 groups
            unsigned e = (o2 + 1) >> 3;     // epoch
            asm volatile("st.release.gpu.global.u32 [%0], %1;"
                         :: "l"(&g_rel[0]), "r"(e) : "memory");
        }
    }
}
__device__ __forceinline__ void bar_wait(unsigned e) {
    unsigned v;
    do {
        asm volatile("ld.acquire.gpu.global.u32 %0, [%1];"
                     : "=r"(v) : "l"(&g_rel[0]) : "memory");
    } while (v < e);
}

__global__ void reset_bar_kernel() {
    int i = threadIdx.x;
    if (i < 8) g_grp[i * 32] = 0;
    if (i == 8) g_root[0] = 0;
    if (i == 9) g_rel[0] = 0;
}

// ---------------- SGEMM (unchanged, known-good) ----------------
__global__ __launch_bounds__(256, 2) void sgemm_kernel(
    const float* __restrict__ A, int amode, int K,
    const float* __restrict__ W0g, const float* __restrict__ W1g, const float* __restrict__ W2g,
    const float* __restrict__ b0g, const float* __restrict__ b1g, const float* __restrict__ b2g,
    int ngate, float* __restrict__ C, int omode, int ldc)
{
    __shared__ float As[8][128];
    __shared__ float Bs[8][132];

    const int tid = threadIdx.x;
    const int bm = blockIdx.x;
    const int ncol0 = blockIdx.y * 128;
    const int gate = ncol0 / ngate;
    const float* W    = (gate == 0) ? W0g : (gate == 1) ? W1g : W2g;
    const float* bias = (gate == 0) ? b0g : (gate == 1) ? b1g : b2g;
    const int ng_off = ncol0 - gate * ngate;

    const int tx = tid & 15;
    const int ty = tid >> 4;

    float acc[8][8];
#pragma unroll
    for (int i = 0; i < 8; i++)
#pragma unroll
        for (int j = 0; j < 8; j++) acc[i][j] = 0.f;

    const int arow = tid >> 1;
    const int ak = (tid & 1) * 4;
    const int grow = bm * 128 + arow;
    long aoff;
    if (amode == 0) aoff = (long)(grow & 31) * (SS * II) + (long)(grow >> 5) * II;
    else            aoff = (long)grow * K;

    const int bk = tid >> 5;
    const int bn = (tid & 31) * 4;

    for (int kk = 0; kk < K; kk += 8) {
        float4 av = *(const float4*)(A + aoff + (kk + ak));
        As[ak + 0][arow] = av.x;
        As[ak + 1][arow] = av.y;
        As[ak + 2][arow] = av.z;
        As[ak + 3][arow] = av.w;
        float4 wv = *(const float4*)(W + (long)(kk + bk) * ngate + (ng_off + bn));
        *(float4*)&Bs[bk][bn] = wv;
        __syncthreads();
#pragma unroll
        for (int k = 0; k < 8; k++) {
            float rm[8], rn[8];
            *(float4*)&rm[0] = *(const float4*)&As[k][ty * 8];
            *(float4*)&rm[4] = *(const float4*)&As[k][ty * 8 + 4];
            *(float4*)&rn[0] = *(const float4*)&Bs[k][tx * 8];
            *(float4*)&rn[4] = *(const float4*)&Bs[k][tx * 8 + 4];
#pragma unroll
            for (int i = 0; i < 8; i++)
#pragma unroll
                for (int j = 0; j < 8; j++)
                    acc[i][j] += rm[i] * rn[j];
        }
        __syncthreads();
    }

#pragma unroll
    for (int i = 0; i < 8; i++) {
        int row = bm * 128 + ty * 8 + i;
        long obase;
        if (omode == 0) obase = (long)row * ldc + ncol0;
        else            obase = (long)(row & 31) * (SS * OO) + (long)(row >> 5) * OO + ncol0;
#pragma unroll
        for (int j = 0; j < 8; j++)
            C[obase + tx * 8 + j] = acc[i][j] + bias[ng_off + tx * 8 + j];
    }
}

// ---------------- persistent GRU recurrence ----------------
// CTA owns 4 columns c0..c0+3 of z, r, g. Lane = batch, warp = K-chunk of 64,
// warp-self-contained cp.async staging. Phase A split: r-dot -> store r*h ->
// arrive(A) -> z-dot (hides barrier) -> wait(A). Hout + Abuf prefetch hidden
// in barrier B's shadow.
__global__ void __launch_bounds__(256, 1) gru_recur_kernel(
    const float* __restrict__ Abuf,
    const float* __restrict__ Whz, const float* __restrict__ Whr, const float* __restrict__ Whg,
    float* __restrict__ hcur, float* __restrict__ Hout,
    float* __restrict__ rhbuf)
{
    extern __shared__ float smf[];
    float* wA   = smf;                   // [8][512]  z cols 0-3, r cols 4-7 (k-major)
    float* wB   = wA + 8 * 512;          // [4][512]  g cols
    float* h_s  = wB + 4 * 512;          // [32][HSTRIDE]  h, reused for r*h
    float* red  = h_s + 32 * HSTRIDE;    // [8 warps][4 cols][32 b]
    float* z_s  = red + 8 * 128;         // [4][32]
    float* hcol = z_s + 128;             // [4][32]  CTA's own h columns (persistent)

    const int tid = threadIdx.x;
    const int cta = blockIdx.x;
    const int grp = cta >> 4;
    const int c0 = cta * 4;
    const int lane = tid & 31, kw = tid >> 5;
    const int rb = tid & 31, rc = tid >> 5;   // reduce mapping (b, col), tid<128
    const int kbase = kw * 64;

    // stage step-invariant weights into SMEM (once)
    for (int idx = tid; idx < 8 * 512; idx += 256) {
        int c = idx >> 9, k = idx & 511;
        const float* Wm = (c < 4) ? Whz : Whr;
        wA[idx] = Wm[k * 512 + c0 + (c & 3)];
    }
    for (int idx = tid; idx < 4 * 512; idx += 256) {
        int c = idx >> 9, k = idx & 511;
        wB[idx] = Whg[k * 512 + c0 + c];
    }
    if (tid < 128) hcol[tid] = hcur[rb * 512 + c0 + rc];
    __syncthreads();

    unsigned ep = 0;

    // prefetch step-0 Abuf terms
    float pZ = 0.f, pR = 0.f, pG = 0.f;
    if (tid < 128) {
        const float* ab = Abuf + (size_t)rb * 1536 + c0 + rc;
        pZ = __ldg(ab);
        pR = __ldg(ab + 512);
        pG = __ldg(ab + 1024);
    }

    for (int t = 0; t < SS; t++) {
        // ---- stage h: warp kw copies ONLY its K-chunk [kbase, kbase+64) ----
#pragma unroll
        for (int it = 0; it < 16; it++) {
            int e = it * 32 + lane;            // 0..511
            int row = e >> 4, f4 = e & 15;
            cp_async16(&h_s[row * HSTRIDE + kbase + f4 * 4],
                       hcur + row * 512 + kbase + f4 * 4);
        }
        cp_commit();
        cp_wait<0>();
        __syncwarp();

        // ---- r-dot: 4 r cols over this warp's K-chunk ----
        {
            float acc[4] = {0.f, 0.f, 0.f, 0.f};
            const float* hp = h_s + lane * HSTRIDE + kbase;
            const float* wp = wA + 4 * 512 + kbase;
#pragma unroll
            for (int k4 = 0; k4 < 16; k4++) {
                float4 h4 = *(const float4*)(hp + k4 * 4);
#pragma unroll
                for (int c = 0; c < 4; c++) {
                    float4 w4 = *(const float4*)(wp + c * 512 + k4 * 4);
                    acc[c] += h4.x * w4.x + h4.y * w4.y + h4.z * w4.z + h4.w * w4.w;
                }
            }
#pragma unroll
            for (int c = 0; c < 4; c++) red[kw * 128 + c * 32 + lane] = acc[c];
        }
        __syncthreads();

        // ---- r reduce + store r*h ----
        if (tid < 128) {
            float s = pR;
#pragma unroll
            for (int w = 0; w < 8; w++) s += red[w * 128 + tid];
            float rg = 1.f / (1.f + __expf(-s));
            __stcg(&rhbuf[rb * 512 + c0 + rc], rg * hcol[tid]);
        }
        __syncthreads();                 // CTA's rh stores done -> arrive
        if (tid == 0) bar_arrive(grp);
        unsigned epA = ++ep;

        // ---- z-dot (hides barrier A) ----
        {
            float acc[4] = {0.f, 0.f, 0.f, 0.f};
            const float* hp = h_s + lane * HSTRIDE + kbase;
            const float* wp = wA + kbase;
#pragma unroll
            for (int k4 = 0; k4 < 16; k4++) {
                float4 h4 = *(const float4*)(hp + k4 * 4);
#pragma unroll
                for (int c = 0; c < 4; c++) {
                    float4 w4 = *(const float4*)(wp + c * 512 + k4 * 4);
                    acc[c] += h4.x * w4.x + h4.y * w4.y + h4.z * w4.z + h4.w * w4.w;
                }
            }
#pragma unroll
            for (int c = 0; c < 4; c++) red[kw * 128 + c * 32 + lane] = acc[c];
        }
        __syncthreads();
        if (tid < 128) {
            float s = pZ;
#pragma unroll
            for (int w = 0; w < 8; w++) s += red[w * 128 + tid];
            z_s[tid] = 1.f / (1.f + __expf(-s));
        }

        if (tid == 0) bar_wait(epA);
        __syncthreads();

        // ---- stage r*h into h_s (warp-self-contained) ----
#pragma unroll
        for (int it = 0; it < 16; it++) {
            int e = it * 32 + lane;
            int row = e >> 4, f4 = e & 15;
            cp_async16(&h_s[row * HSTRIDE + kbase + f4 * 4],
                       rhbuf + row * 512 + kbase + f4 * 4);
        }
        cp_commit();
        cp_wait<0>();
        __syncwarp();

        // ---- g-dot: 4 g cols ----
        {
            float acc[4] = {0.f, 0.f, 0.f, 0.f};
            const float* rp = h_s + lane * HSTRIDE + kbase;
            const float* wp = wB + kbase;
#pragma unroll
            for (int k4 = 0; k4 < 16; k4++) {
                float4 h4 = *(const float4*)(rp + k4 * 4);
#pragma unroll
                for (int c = 0; c < 4; c++) {
                    float4 w4 = *(const float4*)(wp + c * 512 + k4 * 4);
                    acc[c] += h4.x * w4.x + h4.y * w4.y + h4.z * w4.z + h4.w * w4.w;
                }
            }
#pragma unroll
            for (int c = 0; c < 4; c++) red[kw * 128 + c * 32 + lane] = acc[c];
        }
        __syncthreads();

        // ---- g reduce + h update ----
        float hn = 0.f;
        if (tid < 128) {
            float s = pG;
#pragma unroll
            for (int w = 0; w < 8; w++) s += red[w * 128 + tid];
            float g = tanhf(s);
            float z = z_s[tid];
            float ho = hcol[tid];
            hn = z * ho + (1.f - z) * g;
            hcol[tid] = hn;
            __stcg(&hcur[rb * 512 + c0 + rc], hn);
        }
        __syncthreads();                 // hcur stores done -> arrive
        if (tid == 0) bar_arrive(grp);
        unsigned epB = ++ep;

        // ---- barrier B shadow: Hout write + next step's Abuf prefetch ----
        if (tid < 128) {
            Hout[(size_t)(t * 32 + rb) * 512 + c0 + rc] = hn;
            if (t + 1 < SS) {
                const float* ab = Abuf + (size_t)((t + 1) * 32 + rb) * 1536 + c0 + rc;
                pZ = __ldg(ab);
                pR = __ldg(ab + 512);
                pG = __ldg(ab + 1024);
            }
        }

        if (tid == 0) bar_wait(epB);
        __syncthreads();
    }
}

// ---------------- small helpers ----------------
__global__ void init_h_kernel(const float* __restrict__ h0, float* __restrict__ hc) {
    int i = blockIdx.x * 256 + threadIdx.x;
    if (i < 2 * BB * HH) {
        int l = i >> 14, rem = i & 16383, b = rem >> 9, h = rem & 511;
        hc[i] = h0[b * 1024 + l * 512 + h];
    }
}

__global__ void copy_hidden_kernel(float* __restrict__ out, const float* __restrict__ hc) {
    int i = blockIdx.x * 256 + threadIdx.x;
    if (i < BB * 2 * HH) {
        int b = i >> 10, rem = i & 1023;
        int l = rem >> 9, h = rem & 511;
        out[i] = hc[l * (BB * HH) + (b << 9) + h];
    }
}

// ---------------- launch ----------------
extern "C" void kernel_launch(void* const* d_in, const int* in_sizes, int n_in,
                              void* d_out, int out_size)
{
    const float* x    = (const float*)d_in[0];
    const float* h0   = (const float*)d_in[1];
    const float* W0xz = (const float*)d_in[2];
    const float* W0hz = (const float*)d_in[3];
    const float* b0z  = (const float*)d_in[4];
    const float* W0xr = (const float*)d_in[5];
    const float* W0hr = (const float*)d_in[6];
    const float* b0r  = (const float*)d_in[7];
    const float* W0xg = (const float*)d_in[8];
    const float* W0hg = (const float*)d_in[9];
    const float* b0g  = (const float*)d_in[10];
    const float* W1xz = (const float*)d_in[11];
    const float* W1hz = (const float*)d_in[12];
    const float* b1z  = (const float*)d_in[13];
    const float* W1xr = (const float*)d_in[14];
    const float* W1hr = (const float*)d_in[15];
    const float* b1r  = (const float*)d_in[16];
    const float* W1xg = (const float*)d_in[17];
    const float* W1hg = (const float*)d_in[18];
    const float* b1g  = (const float*)d_in[19];
    const float* Wy   = (const float*)d_in[20];
    const float* by   = (const float*)d_in[21];
    float* out = (float*)d_out;

    float *Abuf, *H0, *H1, *hc, *rhb;
    cudaGetSymbolAddress((void**)&Abuf, g_Abuf);
    cudaGetSymbolAddress((void**)&H0,   g_H0);
    cudaGetSymbolAddress((void**)&H1,   g_H1);
    cudaGetSymbolAddress((void**)&hc,   g_hc);
    cudaGetSymbolAddress((void**)&rhb,  g_rhbuf);

    // smem: wA 8*512 + wB 4*512 + h_s 32*HSTRIDE + red 8*128 + z 128 + hcol 128
    const size_t smem = (size_t)(8 * 512 + 4 * 512 + 32 * HSTRIDE + 8 * 128 + 256)
                        * sizeof(float);   // ~93.5 KB
    cudaFuncSetAttribute(gru_recur_kernel,
                         cudaFuncAttributeMaxDynamicSharedMemorySize, (int)smem);

    init_h_kernel<<<128, 256>>>(h0, hc);

    dim3 gproj(512, 12);  // M=65536/128, N=1536/128

    // layer 0
    sgemm_kernel<<<gproj, 256>>>(x, 0, II, W0xz, W0xr, W0xg, b0z, b0r, b0g,
                                 512, Abuf, 0, 1536);
    reset_bar_kernel<<<1, 32>>>();
    gru_recur_kernel<<<RGRID, 256, smem>>>(Abuf, W0hz, W0hr, W0hg,
                                           hc, H0, rhb);

    // layer 1
    sgemm_kernel<<<gproj, 256>>>(H0, 1, HH, W1xz, W1xr, W1xg, b1z, b1r, b1g,
                                 512, Abuf, 0, 1536);
    reset_bar_kernel<<<1, 32>>>();
    gru_recur_kernel<<<RGRID, 256, smem>>>(Abuf, W1hz, W1hr, W1hg,
                                           hc + BB * HH, H1, rhb);

    // output head
    dim3 ghead(512, 1);
    sgemm_kernel<<<ghead, 256>>>(H1, 1, HH, Wy, Wy, Wy, by, by, by,
                                 128, out, 1, 0);

    if (out_size >= BB * SS * OO + BB * 2 * HH) {
        copy_hidden_kernel<<<128, 256>>>(out + BB * SS * OO, hc);
    }
}